// round 13
// baseline (speedup 1.0000x reference)
#include <cuda_runtime.h>
#include <math.h>

#define NQ      1024
#define LQ      128
#define KPOS    8
#define NNEG    2048
#define NLABPOS 8192
#define NW      10240
#define NR      11264
#define DIM     256
#define NHEAD   4
#define HDIM    64
#define NP      16
#define NM      32
#define NLAB    131072

// ---------------- device scratch ----------------
__device__ __align__(16) float g_raw[NR * DIM];
__device__ __align__(16) float g_poly[NR * NHEAD * NP];
__device__ __align__(16) float g_prf [NR * NHEAD * 64];
__device__ __align__(16) float g_wT[320 * HDIM];
__device__ float g_G[NHEAD * NP * 64];
__device__ float g_acc[2];
__device__ int   g_cnt;
__device__ int   g_cols[NW];
__device__ int   g_pos[NW];

__device__ __forceinline__ void slay_consts(float s[2], float sq2s[2], float emult[2]) {
    const double R2 = 1.4142135623730951;
    const double C  = 2.000001;
    double n0 = (2.0 - R2) / C, n1 = (2.0 + R2) / C;
    double w0 = ((2.0 + R2) / 4.0) / C, w1 = ((2.0 - R2) / 4.0) / C;
    s[0] = (float)n0; s[1] = (float)n1;
    sq2s[0] = sqrtf(2.0f * s[0]); sq2s[1] = sqrtf(2.0f * s[1]);
    float invSqM = (float)(1.0 / sqrt(32.000001));
    emult[0] = invSqM * (float)sqrt(w0);
    emult[1] = invSqM * (float)sqrt(w1);
}

// =====================================================================
// Kernel A: fused [query-gather | sort+init | weight-fold], 256 thr/blk
// =====================================================================
__global__ void kA(const int* __restrict__ idx, const float* __restrict__ mask,
                   const float* __restrict__ table,
                   const int* __restrict__ labels, const int* __restrict__ negidx,
                   const float* __restrict__ anchors, const float* __restrict__ omega) {
    int t = threadIdx.x;
    int b = blockIdx.x;

    if (b < NQ) {
        __shared__ int   sIdx[LQ];
        __shared__ float sMask[LQ];
        __shared__ float sRed[256];
        if (t < LQ) { sIdx[t] = idx[b * LQ + t]; sMask[t] = mask[b * LQ + t]; }
        __syncthreads();
        sRed[t] = (t < LQ) ? sMask[t] : 0.f;
        __syncthreads();
        for (int s = 128; s > 0; s >>= 1) { if (t < s) sRed[t] += sRed[t + s]; __syncthreads(); }
        float inv = 1.f / fmaxf(sRed[0], 1.f);
        float a0 = 0.f, a1 = 0.f;
        #pragma unroll 8
        for (int l = 0; l < LQ; l += 2) {
            a0 = fmaf(__ldg(&table[(size_t)sIdx[l]     * DIM + t]), sMask[l],     a0);
            a1 = fmaf(__ldg(&table[(size_t)sIdx[l + 1] * DIM + t]), sMask[l + 1], a1);
        }
        g_raw[b * DIM + t] = (a0 + a1) * inv;
    } else if (b == NQ) {
        __shared__ int hist[1024];
        __shared__ int cur[1024];
        __shared__ int wsum[8];
        __shared__ int woff[8];
        #pragma unroll
        for (int i = 0; i < 4; ++i) hist[t + i * 256] = 0;
        for (int i = t; i < NHEAD * NP * 64; i += 256) g_G[i] = 0.f;
        if (t < 2) g_acc[t] = 0.f;
        if (t == 0) g_cnt = 0;
        __syncthreads();
        #pragma unroll 4
        for (int k = 0; k < 40; ++k) {
            int j = k * 256 + t;
            int col = (j < NLABPOS) ? max(__ldg(&labels[j]), 0) : __ldg(&negidx[j - NLABPOS]);
            atomicAdd(&hist[col >> 7], 1);
        }
        __syncthreads();
        int b0 = t * 4;
        int h0 = hist[b0], h1 = hist[b0+1], h2 = hist[b0+2], h3 = hist[b0+3];
        int tsum = h0 + h1 + h2 + h3;
        int lane = t & 31, wid = t >> 5;
        int v = tsum;
        #pragma unroll
        for (int off = 1; off < 32; off <<= 1) {
            int n = __shfl_up_sync(0xffffffff, v, off);
            if (lane >= off) v += n;
        }
        if (lane == 31) wsum[wid] = v;
        __syncthreads();
        if (t == 0) {
            int r = 0;
            for (int w = 0; w < 8; ++w) { woff[w] = r; r += wsum[w]; }
        }
        __syncthreads();
        int texcl = v - tsum + woff[wid];
        cur[b0]     = texcl;
        cur[b0 + 1] = texcl + h0;
        cur[b0 + 2] = texcl + h0 + h1;
        cur[b0 + 3] = texcl + h0 + h1 + h2;
        __syncthreads();
        #pragma unroll 4
        for (int k = 0; k < 40; ++k) {
            int j = k * 256 + t;
            int col = (j < NLABPOS) ? max(__ldg(&labels[j]), 0) : __ldg(&negidx[j - NLABPOS]);
            int p = atomicAdd(&cur[col >> 7], 1);
            g_cols[p] = col;
            g_pos[p]  = j;
        }
    } else {
        int hu = b - (NQ + 1);            // 0..319
        int h = hu / 80, u = hu - h * 80;
        float sC[2], sq2s[2], emult[2];
        slay_consts(sC, sq2s, emult);
        __shared__ float red[HDIM];
        if (u < NP) {
            float val = 0.f;
            if (t < HDIM) { val = anchors[u * HDIM + t]; red[t] = val * val; }
            __syncthreads();
            #pragma unroll
            for (int s = 32; s > 0; s >>= 1) {
                if (t < s && t + s < HDIM) red[t] += red[t + s];
                __syncthreads();
            }
            if (t < HDIM) g_wT[hu * HDIM + t] = val * (1.f / sqrtf(red[0]));
        } else if (t < HDIM) {
            int q = u - NP;
            int r = q >> 5, m = q & 31;
            g_wT[hu * HDIM + t] =
                omega[(size_t)((r * 4 + h) * HDIM + t) * NM + m] * 0.125f * sq2s[r];
        }
    }
}

// =====================================================================
// Kernel B: sorted gather of W columns, 8 entries per block
// =====================================================================
__global__ void kB_gatherW(const float* __restrict__ kmat) {
    int i0 = blockIdx.x * 8;     // grid 1280
    int t  = threadIdx.x;        // 256
    __shared__ int sCol[8], sJ[8];
    if (t < 8) { sCol[t] = g_cols[i0 + t]; sJ[t] = g_pos[i0 + t]; }
    __syncthreads();
    float v[8];
    #pragma unroll
    for (int e = 0; e < 8; ++e)
        v[e] = __ldg(&kmat[(size_t)t * NLAB + sCol[e]]);
    #pragma unroll
    for (int e = 0; e < 8; ++e)
        g_raw[(size_t)(NQ + sJ[e]) * DIM + t] = v[e];
}

// =====================================================================
// Kernel C: normalize + features; neg blocks also accumulate G
// =====================================================================
#define RPB 32
#define TPB2 320
__global__ void kC_features() {
    __shared__ float4 zs4[RPB * 64];    // 32 KB (first 8 KB reused as poly tile in tail)
    __shared__ float ssq[RPB * NHEAD];
    __shared__ float scal[RPB * NHEAD];
    int t = threadIdx.x;
    int row0 = blockIdx.x * RPB;
    bool negBlock = (row0 >= NQ + NLABPOS);

    const float4* src = (const float4*)(g_raw + (size_t)row0 * DIM);
    for (int i = t; i < RPB * 64; i += TPB2) zs4[i] = src[i];
    __syncthreads();

    if (t < RPB * NHEAD) {
        int rr = t >> 2, h = t & 3;
        const float4* z = &zs4[rr * 64 + h * 16];
        float s = 0.f;
        #pragma unroll
        for (int i = 0; i < 16; ++i) {
            float4 v = z[i];
            s += v.x * v.x + v.y * v.y + v.z * v.z + v.w * v.w;
        }
        ssq[t] = s;
    }
    __syncthreads();
    if (t < RPB) {
        float s0 = ssq[t*4], s1 = ssq[t*4+1], s2 = ssq[t*4+2], s3 = ssq[t*4+3];
        float invf = 1.f / fmaxf(sqrtf(s0 + s1 + s2 + s3), 1e-4f);
        float sh[4] = {s0, s1, s2, s3};
        #pragma unroll
        for (int h = 0; h < 4; ++h) {
            float nh = sqrtf(sh[h]) * invf;
            scal[t*4 + h] = invf / fmaxf(nh, 1e-4f);
        }
    }
    __syncthreads();

    float sC[2], sq2s[2], emult[2];
    slay_consts(sC, sq2s, emult);

    int h = t / 80;
    int u = t - h * 80;
    bool isPoly = (u < NP);
    int q = u - NP;
    int r = (q >> 5) & 1;
    float biasR  = isPoly ? 0.f : sC[r];
    float emultR = isPoly ? 0.f : emult[r];
    const float4* wp = (const float4*)&g_wT[(h * 80 + u) * HDIM];

    for (int c0 = 0; c0 < RPB; c0 += 8) {
        float acc[8] = {0,0,0,0,0,0,0,0};
        const float4* zb = &zs4[c0 * 64 + h * 16];
        #pragma unroll
        for (int d4 = 0; d4 < 16; ++d4) {
            float4 w = __ldg(wp + d4);
            #pragma unroll
            for (int i = 0; i < 8; ++i) {
                float4 z = zb[i * 64 + d4];
                acc[i] = fmaf(w.x, z.x,
                         fmaf(w.y, z.y,
                         fmaf(w.z, z.z,
                         fmaf(w.w, z.w, acc[i]))));
            }
        }
        #pragma unroll
        for (int i = 0; i < 8; ++i) {
            int rr = c0 + i;
            int g  = row0 + rr;
            float v = acc[i] * scal[rr * 4 + h];
            if (isPoly) {
                v = fminf(fmaxf(v, -1.f), 1.f);
                g_poly[(size_t)g * 64 + h * NP + u] = v * v * 0.25f;
            } else {
                float arg = fminf(fmaxf(v - biasR, -20.f), 20.f);
                g_prf[(size_t)g * 256 + h * 64 + q] = expf(arg) * emultR;
            }
        }
    }

    if (!negBlock) return;

    // ---- fused G accumulation (register outer-product; own rows are
    //      visible after __syncthreads, L1/L2-hot) ----
    __syncthreads();                       // all feature writes of this block done
    float* sPolyT = (float*)zs4;           // reuse 8 KB
    if (t < 256) {
        float4* pd = (float4*)sPolyT;
        const float4* ps = (const float4*)&g_poly[(size_t)row0 * 64];
        pd[t]       = ps[t];
        pd[t + 256] = ps[t + 256];
    }
    __syncthreads();
    if (t < 256) {
        int lane = t & 31, w = t >> 5;
        int hh = w >> 1;                   // 0..3
        int m  = (w & 1) * 32 + lane;      // 0..63
        float acc[16];
        #pragma unroll
        for (int p = 0; p < 16; ++p) acc[p] = 0.f;
        const float* prfBase = &g_prf[(size_t)row0 * 256 + hh * 64 + m];
        #pragma unroll 8
        for (int n = 0; n < 32; ++n) {
            float pv = __ldg(prfBase + (size_t)n * 256);
            const float* pp = &sPolyT[n * 64 + hh * 16];
            #pragma unroll
            for (int p = 0; p < 16; ++p)
                acc[p] = fmaf(pp[p], pv, acc[p]);
        }
        #pragma unroll
        for (int p = 0; p < 16; ++p)
            atomicAdd(&g_G[(hh * 16 + p) * 64 + m], acc[p]);
    }
}

// =====================================================================
// Kernel D: one query per block, grid 1024 x 256 thr.
// =====================================================================
__global__ void kD_final(const float* __restrict__ lmask, float* __restrict__ out) {
    __shared__ float sPoly[64];
    __shared__ float sPrf[256];
    __shared__ float sPart[8];
    int t = threadIdx.x;      // 256
    int b = blockIdx.x;       // 1024
    int lane = t & 31, wid = t >> 5;

    if (t < 64) sPoly[t] = g_poly[(size_t)b * 64 + t];
    sPrf[t] = g_prf[(size_t)b * 256 + t];
    __syncthreads();

    int h = t >> 6, m = t & 63;
    float T = 0.f;
    #pragma unroll
    for (int p = 0; p < NP; ++p)
        T = fmaf(sPoly[h * NP + p], __ldg(&g_G[(h * NP + p) * 64 + m]), T);
    float nval = T * sPrf[t];
    #pragma unroll
    for (int off = 16; off > 0; off >>= 1)
        nval += __shfl_xor_sync(0xffffffff, nval, off);
    if (lane == 0) sPart[wid] = nval;
    __syncthreads();

    if (wid == 0) {
        float negSum = sPart[0] + sPart[1] + sPart[2] + sPart[3]
                     + sPart[4] + sPart[5] + sPart[6] + sPart[7];

        int k  = lane >> 2;
        int hh = lane & 3;
        int wrow = NQ + b * KPOS + k;
        float A = 0.f, B = 0.f;
        const float* pw = &g_poly[(size_t)wrow * 64 + hh * NP];
        #pragma unroll
        for (int p = 0; p < NP; ++p) A = fmaf(sPoly[hh * NP + p], __ldg(&pw[p]), A);
        const float* rw = &g_prf[(size_t)wrow * 256 + hh * 64];
        const float* rq = &sPrf[hh * 64];
        #pragma unroll 8
        for (int mm = 0; mm < 64; ++mm) B = fmaf(rq[mm], __ldg(&rw[mm]), B);
        float sc = A * B;
        sc += __shfl_xor_sync(0xffffffff, sc, 1);
        sc += __shfl_xor_sync(0xffffffff, sc, 2);

        float pall[KPOS];
        #pragma unroll
        for (int k2 = 0; k2 < KPOS; ++k2)
            pall[k2] = __shfl_sync(0xffffffff, sc, k2 * 4);

        if (lane == 0) {
            float S = negSum + (float)NNEG * 1e-8f;
            #pragma unroll
            for (int k2 = 0; k2 < KPOS; ++k2) S += pall[k2] + 1e-8f;
            float logS = logf(S);
            float num = 0.f, den = 0.f;
            #pragma unroll
            for (int k2 = 0; k2 < KPOS; ++k2) {
                float lm = __ldg(&lmask[b * KPOS + k2]);
                num += lm * (logf(pall[k2] + 1e-8f) - logS);
                den += lm;
            }
            atomicAdd(&g_acc[0], num);
            atomicAdd(&g_acc[1], den);
            __threadfence();
            int ticket = atomicAdd(&g_cnt, 1);
            if (ticket == NQ - 1)
                out[0] = -g_acc[0] / (g_acc[1] + 1e-6f);
        }
    }
}

// ---------------- launch ---------------------------------------------------
extern "C" void kernel_launch(void* const* d_in, const int* in_sizes, int n_in,
                              void* d_out, int out_size) {
    const int*   indices = (const int*)  d_in[0];
    const float* mask    = (const float*)d_in[1];
    const int*   labels  = (const int*)  d_in[2];
    const float* lmask   = (const float*)d_in[3];
    const int*   negidx  = (const int*)  d_in[4];
    const float* table   = (const float*)d_in[5];
    const float* kmat    = (const float*)d_in[6];
    const float* omega   = (const float*)d_in[7];
    const float* anchors = (const float*)d_in[8];
    float* out = (float*)d_out;

    kA         <<<NQ + 1 + 320, 256>>>(indices, mask, table, labels, negidx, anchors, omega);
    kB_gatherW <<<NW / 8, 256>>>(kmat);
    kC_features<<<NR / RPB, TPB2>>>();
    kD_final   <<<NQ, 256>>>(lmask, out);
}

// round 14
// speedup vs baseline: 1.0778x; 1.0778x over previous
#include <cuda_runtime.h>
#include <math.h>

#define NQ      1024
#define LQ      128
#define KPOS    8
#define NNEG    2048
#define NLABPOS 8192
#define NW      10240
#define NR      11264
#define DIM     256
#define NHEAD   4
#define HDIM    64
#define NP      16
#define NM      32
#define NLAB    131072

// ---------------- device scratch ----------------
__device__ __align__(16) float g_raw[NR * DIM];
__device__ __align__(16) float g_poly[NR * NHEAD * NP];
__device__ __align__(16) float g_prf [NR * NHEAD * 64];
__device__ __align__(16) float g_wT[320 * HDIM];
__device__ float g_G[NHEAD * NP * 64];
__device__ float g_acc[2];
__device__ int   g_cnt;
__device__ int   g_cols[NW];
__device__ int   g_pos[NW];

__device__ __forceinline__ void slay_consts(float s[2], float sq2s[2], float emult[2]) {
    const double R2 = 1.4142135623730951;
    const double C  = 2.000001;
    double n0 = (2.0 - R2) / C, n1 = (2.0 + R2) / C;
    double w0 = ((2.0 + R2) / 4.0) / C, w1 = ((2.0 - R2) / 4.0) / C;
    s[0] = (float)n0; s[1] = (float)n1;
    sq2s[0] = sqrtf(2.0f * s[0]); sq2s[1] = sqrtf(2.0f * s[1]);
    float invSqM = (float)(1.0 / sqrt(32.000001));
    emult[0] = invSqM * (float)sqrt(w0);
    emult[1] = invSqM * (float)sqrt(w1);
}

// =====================================================================
// Kernel A: fused [query-gather | sort+init | weight-fold], 256 thr/blk
// =====================================================================
__global__ void kA(const int* __restrict__ idx, const float* __restrict__ mask,
                   const float* __restrict__ table,
                   const int* __restrict__ labels, const int* __restrict__ negidx,
                   const float* __restrict__ anchors, const float* __restrict__ omega) {
    int t = threadIdx.x;
    int b = blockIdx.x;

    if (b < NQ) {
        __shared__ int   sIdx[LQ];
        __shared__ float sMask[LQ];
        __shared__ float sRed[256];
        if (t < LQ) { sIdx[t] = idx[b * LQ + t]; sMask[t] = mask[b * LQ + t]; }
        __syncthreads();
        sRed[t] = (t < LQ) ? sMask[t] : 0.f;
        __syncthreads();
        for (int s = 128; s > 0; s >>= 1) { if (t < s) sRed[t] += sRed[t + s]; __syncthreads(); }
        float inv = 1.f / fmaxf(sRed[0], 1.f);
        float a0 = 0.f, a1 = 0.f;
        #pragma unroll 8
        for (int l = 0; l < LQ; l += 2) {
            a0 = fmaf(__ldg(&table[(size_t)sIdx[l]     * DIM + t]), sMask[l],     a0);
            a1 = fmaf(__ldg(&table[(size_t)sIdx[l + 1] * DIM + t]), sMask[l + 1], a1);
        }
        g_raw[b * DIM + t] = (a0 + a1) * inv;
    } else if (b == NQ) {
        __shared__ int hist[1024];
        __shared__ int cur[1024];
        __shared__ int wsum[8];
        __shared__ int woff[8];
        #pragma unroll
        for (int i = 0; i < 4; ++i) hist[t + i * 256] = 0;
        for (int i = t; i < NHEAD * NP * 64; i += 256) g_G[i] = 0.f;
        if (t < 2) g_acc[t] = 0.f;
        if (t == 0) g_cnt = 0;
        __syncthreads();
        #pragma unroll 4
        for (int k = 0; k < 40; ++k) {
            int j = k * 256 + t;
            int col = (j < NLABPOS) ? max(__ldg(&labels[j]), 0) : __ldg(&negidx[j - NLABPOS]);
            atomicAdd(&hist[col >> 7], 1);
        }
        __syncthreads();
        int b0 = t * 4;
        int h0 = hist[b0], h1 = hist[b0+1], h2 = hist[b0+2], h3 = hist[b0+3];
        int tsum = h0 + h1 + h2 + h3;
        int lane = t & 31, wid = t >> 5;
        int v = tsum;
        #pragma unroll
        for (int off = 1; off < 32; off <<= 1) {
            int n = __shfl_up_sync(0xffffffff, v, off);
            if (lane >= off) v += n;
        }
        if (lane == 31) wsum[wid] = v;
        __syncthreads();
        if (t == 0) {
            int r = 0;
            for (int w = 0; w < 8; ++w) { woff[w] = r; r += wsum[w]; }
        }
        __syncthreads();
        int texcl = v - tsum + woff[wid];
        cur[b0]     = texcl;
        cur[b0 + 1] = texcl + h0;
        cur[b0 + 2] = texcl + h0 + h1;
        cur[b0 + 3] = texcl + h0 + h1 + h2;
        __syncthreads();
        #pragma unroll 4
        for (int k = 0; k < 40; ++k) {
            int j = k * 256 + t;
            int col = (j < NLABPOS) ? max(__ldg(&labels[j]), 0) : __ldg(&negidx[j - NLABPOS]);
            int p = atomicAdd(&cur[col >> 7], 1);
            g_cols[p] = col;
            g_pos[p]  = j;
        }
    } else {
        int hu = b - (NQ + 1);            // 0..319
        int h = hu / 80, u = hu - h * 80;
        float sC[2], sq2s[2], emult[2];
        slay_consts(sC, sq2s, emult);
        __shared__ float red[HDIM];
        if (u < NP) {
            float val = 0.f;
            if (t < HDIM) { val = anchors[u * HDIM + t]; red[t] = val * val; }
            __syncthreads();
            #pragma unroll
            for (int s = 32; s > 0; s >>= 1) {
                if (t < s && t + s < HDIM) red[t] += red[t + s];
                __syncthreads();
            }
            if (t < HDIM) g_wT[hu * HDIM + t] = val * (1.f / sqrtf(red[0]));
        } else if (t < HDIM) {
            int q = u - NP;
            int r = q >> 5, m = q & 31;
            g_wT[hu * HDIM + t] =
                omega[(size_t)((r * 4 + h) * HDIM + t) * NM + m] * 0.125f * sq2s[r];
        }
    }
}

// =====================================================================
// Kernel B: sorted gather of W columns, 8 entries per block
// =====================================================================
__global__ void kB_gatherW(const float* __restrict__ kmat) {
    int i0 = blockIdx.x * 8;     // grid 1280
    int t  = threadIdx.x;        // 256
    __shared__ int sCol[8], sJ[8];
    if (t < 8) { sCol[t] = g_cols[i0 + t]; sJ[t] = g_pos[i0 + t]; }
    __syncthreads();
    float v[8];
    #pragma unroll
    for (int e = 0; e < 8; ++e)
        v[e] = __ldg(&kmat[(size_t)t * NLAB + sCol[e]]);
    #pragma unroll
    for (int e = 0; e < 8; ++e)
        g_raw[(size_t)(NQ + sJ[e]) * DIM + t] = v[e];
}

// =====================================================================
// Kernel C: normalize + features
// =====================================================================
#define RPB 32
#define TPB2 320
__global__ void kC_features() {
    __shared__ float4 zs4[RPB * 64];    // 32 KB
    __shared__ float ssq[RPB * NHEAD];
    __shared__ float scal[RPB * NHEAD];
    int t = threadIdx.x;
    int row0 = blockIdx.x * RPB;

    const float4* src = (const float4*)(g_raw + (size_t)row0 * DIM);
    for (int i = t; i < RPB * 64; i += TPB2) zs4[i] = src[i];
    __syncthreads();

    if (t < RPB * NHEAD) {
        int rr = t >> 2, h = t & 3;
        const float4* z = &zs4[rr * 64 + h * 16];
        float s = 0.f;
        #pragma unroll
        for (int i = 0; i < 16; ++i) {
            float4 v = z[i];
            s += v.x * v.x + v.y * v.y + v.z * v.z + v.w * v.w;
        }
        ssq[t] = s;
    }
    __syncthreads();
    if (t < RPB) {
        float s0 = ssq[t*4], s1 = ssq[t*4+1], s2 = ssq[t*4+2], s3 = ssq[t*4+3];
        float invf = 1.f / fmaxf(sqrtf(s0 + s1 + s2 + s3), 1e-4f);
        float sh[4] = {s0, s1, s2, s3};
        #pragma unroll
        for (int h = 0; h < 4; ++h) {
            float nh = sqrtf(sh[h]) * invf;
            scal[t*4 + h] = invf / fmaxf(nh, 1e-4f);
        }
    }
    __syncthreads();

    float sC[2], sq2s[2], emult[2];
    slay_consts(sC, sq2s, emult);

    int h = t / 80;
    int u = t - h * 80;
    bool isPoly = (u < NP);
    int q = u - NP;
    int r = (q >> 5) & 1;
    float biasR  = isPoly ? 0.f : sC[r];
    float emultR = isPoly ? 0.f : emult[r];
    const float4* wp = (const float4*)&g_wT[(h * 80 + u) * HDIM];

    for (int c0 = 0; c0 < RPB; c0 += 8) {
        float acc[8] = {0,0,0,0,0,0,0,0};
        const float4* zb = &zs4[c0 * 64 + h * 16];
        #pragma unroll
        for (int d4 = 0; d4 < 16; ++d4) {
            float4 w = __ldg(wp + d4);
            #pragma unroll
            for (int i = 0; i < 8; ++i) {
                float4 z = zb[i * 64 + d4];
                acc[i] = fmaf(w.x, z.x,
                         fmaf(w.y, z.y,
                         fmaf(w.z, z.z,
                         fmaf(w.w, z.w, acc[i]))));
            }
        }
        #pragma unroll
        for (int i = 0; i < 8; ++i) {
            int rr = c0 + i;
            int g  = row0 + rr;
            float v = acc[i] * scal[rr * 4 + h];
            if (isPoly) {
                v = fminf(fmaxf(v, -1.f), 1.f);
                g_poly[(size_t)g * 64 + h * NP + u] = v * v * 0.25f;
            } else {
                float arg = fminf(fmaxf(v - biasR, -20.f), 20.f);
                g_prf[(size_t)g * 256 + h * 64 + q] = expf(arg) * emultR;
            }
        }
    }
}

// =====================================================================
// Kernel G: register outer-product. 64 blocks x 256 thr (8 warps).
// =====================================================================
__global__ void kG() {
    __shared__ float sPoly[32 * 64];     // 8 KB poly tile
    int t = threadIdx.x;                 // 256
    int lane = t & 31, w = t >> 5;
    int h = w >> 1;                      // 0..3
    int m = (w & 1) * 32 + lane;         // 0..63
    int base = NQ + NLABPOS + blockIdx.x * 32;

    {
        const float4* ps = (const float4*)&g_poly[(size_t)base * 64];
        float4* pd = (float4*)sPoly;
        pd[t]       = ps[t];
        pd[t + 256] = ps[t + 256];
    }
    __syncthreads();

    float acc[16];
    #pragma unroll
    for (int p = 0; p < 16; ++p) acc[p] = 0.f;

    const float* prfBase = &g_prf[(size_t)base * 256 + h * 64 + m];
    #pragma unroll 8
    for (int n = 0; n < 32; ++n) {
        float pv = __ldg(prfBase + (size_t)n * 256);
        const float* pp = &sPoly[n * 64 + h * 16];
        #pragma unroll
        for (int p = 0; p < 16; ++p)
            acc[p] = fmaf(pp[p], pv, acc[p]);
    }
    #pragma unroll
    for (int p = 0; p < 16; ++p)
        atomicAdd(&g_G[(h * 16 + p) * 64 + m], acc[p]);
}

// =====================================================================
// Kernel D v4: one query per block; positives parallel across 8 warps.
// =====================================================================
__global__ void kD_final(const float* __restrict__ lmask, float* __restrict__ out) {
    __shared__ float sPoly[64];
    __shared__ float sPrf[256];
    __shared__ float sPart[8];
    __shared__ float sPos[8];
    int t = threadIdx.x;      // 256
    int b = blockIdx.x;       // 1024
    int lane = t & 31, wid = t >> 5;

    if (t < 64) sPoly[t] = g_poly[(size_t)b * 64 + t];
    sPrf[t] = g_prf[(size_t)b * 256 + t];
    __syncthreads();

    // ---- negSum contribution of element um = t ----
    int h = t >> 6, m = t & 63;
    float T = 0.f;
    #pragma unroll
    for (int p = 0; p < NP; ++p)
        T = fmaf(sPoly[h * NP + p], __ldg(&g_G[(h * NP + p) * 64 + m]), T);
    float nval = T * sPrf[t];
    #pragma unroll
    for (int off = 16; off > 0; off >>= 1)
        nval += __shfl_xor_sync(0xffffffff, nval, off);
    if (lane == 0) sPart[wid] = nval;

    // ---- positive score k = wid, all 8 warps in parallel ----
    {
        int wrow = NQ + b * KPOS + wid;
        int hh  = lane >> 3;       // 0..3
        int idx = lane & 7;        // 0..7
        const float* pw = &g_poly[(size_t)wrow * 64 + hh * NP];
        float a = fmaf(sPoly[hh * NP + idx],     __ldg(&pw[idx]),
                  sPoly[hh * NP + idx + 8] * __ldg(&pw[idx + 8]));
        const float* rw = &g_prf[(size_t)wrow * 256 + hh * 64];
        float bsum = 0.f;
        #pragma unroll
        for (int j = 0; j < 8; ++j) {
            int mm = idx + j * 8;
            bsum = fmaf(sPrf[hh * 64 + mm], __ldg(&rw[mm]), bsum);
        }
        // reduce within 8-lane head groups
        #pragma unroll
        for (int off = 4; off > 0; off >>= 1) {
            a    += __shfl_xor_sync(0xffffffff, a,    off);
            bsum += __shfl_xor_sync(0xffffffff, bsum, off);
        }
        float prod = a * bsum;                 // per-head product
        prod += __shfl_xor_sync(0xffffffff, prod, 8);
        prod += __shfl_xor_sync(0xffffffff, prod, 16);   // sum over 4 heads
        if (lane == 0) sPos[wid] = prod;
    }
    __syncthreads();

    if (t == 0) {
        float negSum = sPart[0] + sPart[1] + sPart[2] + sPart[3]
                     + sPart[4] + sPart[5] + sPart[6] + sPart[7];
        float S = negSum + (float)NNEG * 1e-8f;
        #pragma unroll
        for (int k2 = 0; k2 < KPOS; ++k2) S += sPos[k2] + 1e-8f;
        float logS = logf(S);
        float num = 0.f, den = 0.f;
        #pragma unroll
        for (int k2 = 0; k2 < KPOS; ++k2) {
            float lm = __ldg(&lmask[b * KPOS + k2]);
            num += lm * (logf(sPos[k2] + 1e-8f) - logS);
            den += lm;
        }
        atomicAdd(&g_acc[0], num);
        atomicAdd(&g_acc[1], den);
        __threadfence();
        int ticket = atomicAdd(&g_cnt, 1);
        if (ticket == NQ - 1)
            out[0] = -g_acc[0] / (g_acc[1] + 1e-6f);
    }
}

// ---------------- launch ---------------------------------------------------
extern "C" void kernel_launch(void* const* d_in, const int* in_sizes, int n_in,
                              void* d_out, int out_size) {
    const int*   indices = (const int*)  d_in[0];
    const float* mask    = (const float*)d_in[1];
    const int*   labels  = (const int*)  d_in[2];
    const float* lmask   = (const float*)d_in[3];
    const int*   negidx  = (const int*)  d_in[4];
    const float* table   = (const float*)d_in[5];
    const float* kmat    = (const float*)d_in[6];
    const float* omega   = (const float*)d_in[7];
    const float* anchors = (const float*)d_in[8];
    float* out = (float*)d_out;

    kA         <<<NQ + 1 + 320, 256>>>(indices, mask, table, labels, negidx, anchors, omega);
    kB_gatherW <<<NW / 8, 256>>>(kmat);
    kC_features<<<NR / RPB, TPB2>>>();
    kG         <<<NNEG / 32, 256>>>();
    kD_final   <<<NQ, 256>>>(lmask, out);
}